// round 1
// baseline (speedup 1.0000x reference)
#include <cuda_runtime.h>

#define Bx     2
#define Hx     512
#define Wx     1024
#define HWx    (Hx * Wx)          // 524288
#define Nx     8
#define NSEG   16
#define NBINS  32768
#define BIN_SCALE 16384.0f
#define MINPIX 128.0f

struct Globals {
    unsigned hist[NSEG * NBINS * 2];   // [seg][bin][label] counts  (4 MB)
    float acc[NSEG * 5];               // cnt, sum_e0, sum_e1, sum_s0, sum_s1
    float seed_bg[Bx];
    float var_s[NSEG];
    float fg_s[NSEG];
    float lov[NSEG];
    float params[NSEG * 8];            // c0 c1 sx0 sx1 sm0 sm1 cnt_safe valid
};
__device__ Globals G;

__device__ const float FGW[8] = {10.0f, 10.0f, 10.0f, 40.0f, 80.0f, 100.0f, 60.0f, 20.0f};

__device__ __forceinline__ float wred(float v) {
    v += __shfl_down_sync(0xffffffffu, v, 16);
    v += __shfl_down_sync(0xffffffffu, v, 8);
    v += __shfl_down_sync(0xffffffffu, v, 4);
    v += __shfl_down_sync(0xffffffffu, v, 2);
    v += __shfl_down_sync(0xffffffffu, v, 1);
    return v;
}

__device__ __forceinline__ float sigmoidf_fast(float x) {
    return __fdividef(1.0f, 1.0f + __expf(-x));
}

// ---------------------------------------------------------------- zero scratch
__global__ void k_zero() {
    unsigned* p = reinterpret_cast<unsigned*>(&G);
    unsigned nwords = (unsigned)(sizeof(Globals) / 4);
    for (unsigned i = blockIdx.x * blockDim.x + threadIdx.x; i < nwords;
         i += gridDim.x * blockDim.x)
        p[i] = 0u;
}

// ---------------------------------------------------------------- pass 1
__global__ void __launch_bounds__(256) k_pass1(const float* __restrict__ pred,
                                               const int* __restrict__ bbox,
                                               const int* __restrict__ masks,
                                               int blocksPerB) {
    int b = blockIdx.x / blocksPerB;
    int blk = blockIdx.x % blocksPerB;
    int stride = blocksPerB * blockDim.x;
    const float* pb = pred + (size_t)b * 12 * HWx;
    const int* bbb = bbox + (size_t)b * 9 * HWx;
    const int* mb  = masks + (size_t)b * 8 * HWx;

    float c_[8]  = {0.f,0.f,0.f,0.f,0.f,0.f,0.f,0.f};
    float ae0[8] = {0.f,0.f,0.f,0.f,0.f,0.f,0.f,0.f};
    float ae1[8] = {0.f,0.f,0.f,0.f,0.f,0.f,0.f,0.f};
    float as0[8] = {0.f,0.f,0.f,0.f,0.f,0.f,0.f,0.f};
    float as1[8] = {0.f,0.f,0.f,0.f,0.f,0.f,0.f,0.f};
    float bg = 0.f;

    for (int hw = blk * blockDim.x + threadIdx.x; hw < HWx; hw += stride) {
        int w = hw & (Wx - 1);
        int h = hw >> 10;
        float e0 = tanhf(pb[hw])         + (float)w * (2.0f / 2047.0f);
        float e1 = tanhf(pb[HWx + hw])   + (float)h * (1.0f / 1023.0f);
        float sg0 = pb[2 * HWx + hw];
        float sg1 = pb[3 * HWx + hw];
#pragma unroll
        for (int c = 0; c < 8; c++) {
            float s = sigmoidf_fast(pb[(4 + c) * HWx + hw]);
            if (bbb[(1 + c) * HWx + hw] == 0) bg = fmaf(s, s, bg);
        }
#pragma unroll
        for (int n = 0; n < 8; n++) {
            float mf = (mb[n * HWx + hw] > 0) ? 1.f : 0.f;
            c_[n] += mf;
            ae0[n] = fmaf(mf, e0, ae0[n]);
            ae1[n] = fmaf(mf, e1, ae1[n]);
            as0[n] = fmaf(mf, sg0, as0[n]);
            as1[n] = fmaf(mf, sg1, as1[n]);
        }
    }
    bg = wred(bg);
    if ((threadIdx.x & 31) == 0) atomicAdd(&G.seed_bg[b], bg);
#pragma unroll
    for (int n = 0; n < 8; n++) {
        int seg = b * 8 + n;
        float v;
        v = wred(c_[n]);  if ((threadIdx.x & 31) == 0) atomicAdd(&G.acc[seg * 5 + 0], v);
        v = wred(ae0[n]); if ((threadIdx.x & 31) == 0) atomicAdd(&G.acc[seg * 5 + 1], v);
        v = wred(ae1[n]); if ((threadIdx.x & 31) == 0) atomicAdd(&G.acc[seg * 5 + 2], v);
        v = wred(as0[n]); if ((threadIdx.x & 31) == 0) atomicAdd(&G.acc[seg * 5 + 3], v);
        v = wred(as1[n]); if ((threadIdx.x & 31) == 0) atomicAdd(&G.acc[seg * 5 + 4], v);
    }
}

// ---------------------------------------------------------------- per-instance params
__global__ void k_params() {
    int t = threadIdx.x;
    if (t < NSEG) {
        float cnt = G.acc[t * 5 + 0];
        float cs = fmaxf(cnt, 1.f);
        float inv = 1.f / cs;
        float c0 = G.acc[t * 5 + 1] * inv;
        float c1 = G.acc[t * 5 + 2] * inv;
        float sm0 = G.acc[t * 5 + 3] * inv;
        float sm1 = G.acc[t * 5 + 4] * inv;
        G.params[t * 8 + 0] = c0;
        G.params[t * 8 + 1] = c1;
        G.params[t * 8 + 2] = expf(sm0 * 10.f);
        G.params[t * 8 + 3] = expf(sm1 * 10.f);
        G.params[t * 8 + 4] = sm0;
        G.params[t * 8 + 5] = sm1;
        G.params[t * 8 + 6] = cs;
        G.params[t * 8 + 7] = (cnt >= MINPIX) ? 1.f : 0.f;
    }
}

// ---------------------------------------------------------------- pass 2: dist, hist, var, seed_fg
__global__ void __launch_bounds__(256) k_pass3(const float* __restrict__ pred,
                                               const int* __restrict__ masks,
                                               const int* __restrict__ cls_ids,
                                               int blocksPerB) {
    int b = blockIdx.x / blocksPerB;
    int blk = blockIdx.x % blocksPerB;
    int stride = blocksPerB * blockDim.x;

    __shared__ float sp[8][6];
    __shared__ int sch[8];
    if (threadIdx.x < 48) {
        int n = threadIdx.x / 6, k = threadIdx.x % 6;
        sp[n][k] = G.params[(b * 8 + n) * 8 + k];
    }
    if (threadIdx.x < 8) sch[threadIdx.x] = cls_ids[b * 8 + threadIdx.x];
    __syncthreads();

    float c0[8], c1[8], sx0[8], sx1[8], sm0[8], sm1[8];
    int ch[8];
#pragma unroll
    for (int n = 0; n < 8; n++) {
        c0[n] = sp[n][0]; c1[n] = sp[n][1];
        sx0[n] = sp[n][2]; sx1[n] = sp[n][3];
        sm0[n] = sp[n][4]; sm1[n] = sp[n][5];
        ch[n] = sch[n];
    }
    float va[8] = {0.f,0.f,0.f,0.f,0.f,0.f,0.f,0.f};
    float fa[8] = {0.f,0.f,0.f,0.f,0.f,0.f,0.f,0.f};

    const float* pb = pred + (size_t)b * 12 * HWx;
    const int* mb = masks + (size_t)b * 8 * HWx;
    unsigned* hb = &G.hist[(size_t)(b * 8) * NBINS * 2];

    for (int hw = blk * blockDim.x + threadIdx.x; hw < HWx; hw += stride) {
        int w = hw & (Wx - 1);
        int h = hw >> 10;
        float e0 = tanhf(pb[hw])       + (float)w * (2.0f / 2047.0f);
        float e1 = tanhf(pb[HWx + hw]) + (float)h * (1.0f / 1023.0f);
        float sg0 = pb[2 * HWx + hw];
        float sg1 = pb[3 * HWx + hw];
#pragma unroll
        for (int n = 0; n < 8; n++) {
            int lab = mb[n * HWx + hw] > 0;
            float mf = (float)lab;
            float dx = e0 - c0[n], dy = e1 - c1[n];
            float d2 = fmaf(dx * dx, sx0[n], dy * dy * sx1[n]);
            float dist = __expf(-d2);
            float e = lab ? fmaf(-2.f, dist, 2.f) : 2.f * dist;
            int bin = (int)(e * BIN_SCALE);
            bin = min(max(bin, 0), NBINS - 1);
            atomicAdd(&hb[(n * NBINS + bin) * 2 + lab], 1u);
            float d0 = sg0 - sm0[n], d1 = sg1 - sm1[n];
            va[n] = fmaf(mf, fmaf(d0, d0, d1 * d1), va[n]);
            float sv = sigmoidf_fast(pb[(4 + ch[n]) * HWx + hw]);
            float dd = sv - dist;
            fa[n] = fmaf(mf, dd * dd, fa[n]);
        }
    }
#pragma unroll
    for (int n = 0; n < 8; n++) {
        int seg = b * 8 + n;
        float v;
        v = wred(va[n]); if ((threadIdx.x & 31) == 0) atomicAdd(&G.var_s[seg], v);
        v = wred(fa[n]); if ((threadIdx.x & 31) == 0) atomicAdd(&G.fg_s[seg], v);
    }
}

// ---------------------------------------------------------------- Lovász via binned scan
__global__ void __launch_bounds__(1024) k_scan() {
    int seg = blockIdx.x;
    int tid = threadIdx.x;
    int warp = tid >> 5, lane = tid & 31;
    __shared__ unsigned long long wsum[32];
    __shared__ float rs[32];

    double Pd = (double)G.acc[seg * 5 + 0];
    unsigned carry_p = 0, carry_n = 0;
    double lov = 0.0;
    const unsigned long long* hp =
        reinterpret_cast<const unsigned long long*>(&G.hist[(size_t)seg * NBINS * 2]);

    for (int it = 0; it < NBINS / 1024; it++) {
        int bin = NBINS - 1 - (it * 1024 + tid);
        unsigned long long pair = hp[bin];        // lab0 = low u32, lab1 = high u32
        unsigned nn = (unsigned)(pair & 0xffffffffu);
        unsigned np = (unsigned)(pair >> 32);
        unsigned long long inc = pair;
#pragma unroll
        for (int o = 1; o < 32; o <<= 1) {
            unsigned long long t = __shfl_up_sync(0xffffffffu, inc, o);
            if (lane >= o) inc += t;
        }
        if (lane == 31) wsum[warp] = inc;
        __syncthreads();
        if (warp == 0) {
            unsigned long long wv = wsum[lane];
#pragma unroll
            for (int o = 1; o < 32; o <<= 1) {
                unsigned long long t = __shfl_up_sync(0xffffffffu, wv, o);
                if (lane >= o) wv += t;
            }
            wsum[lane] = wv;
        }
        __syncthreads();
        unsigned long long incl = inc + (warp > 0 ? wsum[warp - 1] : 0ull);
        unsigned long long total = wsum[31];
        unsigned cp1 = carry_p + (unsigned)(incl >> 32);
        unsigned cn1 = carry_n + (unsigned)(incl & 0xffffffffu);
        unsigned cp0 = cp1 - np;
        unsigned cn0 = cn1 - nn;
        if (np | nn) {
            double j1 = 1.0 - (Pd - (double)cp1) / fmax(Pd + (double)cn1, 1.0);
            double j0 = 1.0 - (Pd - (double)cp0) / fmax(Pd + (double)cn0, 1.0);
            lov += ((double)bin + 0.5) * (1.0 / 16384.0) * (j1 - j0);
        }
        carry_p += (unsigned)(total >> 32);
        carry_n += (unsigned)(total & 0xffffffffu);
        __syncthreads();
    }
    float lf = wred((float)lov);
    if (lane == 0) rs[warp] = lf;
    __syncthreads();
    if (tid < 32) {
        float v = wred(rs[tid]);
        if (tid == 0) G.lov[seg] = v;
    }
}

// ---------------------------------------------------------------- final combine
__global__ void k_final(const int* __restrict__ cls_ids, float* __restrict__ out) {
    if (threadIdx.x == 0 && blockIdx.x == 0) {
        float total = 0.f;
        for (int b = 0; b < Bx; b++) {
            float obj = 0.f, inst = 0.f, var = 0.f, fg = 0.f;
            for (int n = 0; n < 8; n++) {
                int seg = b * 8 + n;
                float cnt = G.acc[seg * 5 + 0];
                float valid = (cnt >= MINPIX) ? 1.f : 0.f;
                float cs = fmaxf(cnt, 1.f);
                obj += valid;
                inst += G.lov[seg] * valid;
                var += (G.var_s[seg] / (2.f * cs)) * valid;
                fg += FGW[cls_ids[seg]] * G.fg_s[seg] * valid;
            }
            float os = fmaxf(obj, 1.f);
            float seed_l = (G.seed_bg[b] + fg) * (1.0f / (float)HWx);
            total += inst / os + 10.f * (var / os) + seed_l;
        }
        out[0] = total * 0.5f;
    }
}

// ---------------------------------------------------------------- launch
extern "C" void kernel_launch(void* const* d_in, const int* in_sizes, int n_in,
                              void* d_out, int out_size) {
    const float* pred = (const float*)d_in[0];
    const int* bbox   = (const int*)d_in[1];
    const int* masks  = (const int*)d_in[2];
    const int* cls    = (const int*)d_in[3];
    (void)in_sizes; (void)n_in; (void)out_size;

    k_zero<<<512, 256>>>();
    const int bpb = 512;
    k_pass1<<<2 * bpb, 256>>>(pred, bbox, masks, bpb);
    k_params<<<1, 32>>>();
    k_pass3<<<2 * bpb, 256>>>(pred, masks, cls, bpb);
    k_scan<<<NSEG, 1024>>>();
    k_final<<<1, 32>>>(cls, (float*)d_out);
}

// round 4
// speedup vs baseline: 1.3615x; 1.3615x over previous
#include <cuda_runtime.h>
#include <cuda_fp16.h>

#define Bx     2
#define Hx     512
#define Wx     1024
#define HWx    (Hx * Wx)          // 524288
#define NSEG   16
#define NBINS  32768
#define BIN_SCALE 16384.0f
#define MINPIX 128.0f
#define BPB    256                // blocks per batch for the big passes

// ---- separate aligned globals ----
__device__ __align__(16) unsigned long long g_hist[NSEG * NBINS]; // low=neg, high=pos
__device__ __align__(16) float g_acc[NSEG * 6];   // cnt, Se0, Se1, Ss0, Ss1, Q
__device__ __align__(16) float g_seed_bg[Bx];
__device__ __align__(16) float g_fg_s[NSEG];
__device__ __align__(16) float g_lov[NSEG];
__device__ __align__(16) float g_params[NSEG * 4]; // c0 c1 sx0 sx1
// scratch (not zeroed)
__device__ __align__(16) float g_e0s[Bx * HWx];
__device__ __align__(16) float g_e1s[Bx * HWx];
__device__ __align__(16) __half g_seeds[Bx * 8 * HWx];       // [b][c][hw]
__device__ __align__(16) unsigned g_mbits[Bx * HWx / 4];     // byte j: bit n = mask n

__device__ const float FGW[8] = {10.0f, 10.0f, 10.0f, 40.0f, 80.0f, 100.0f, 60.0f, 20.0f};

__device__ __forceinline__ float wred(float v) {
    v += __shfl_down_sync(0xffffffffu, v, 16);
    v += __shfl_down_sync(0xffffffffu, v, 8);
    v += __shfl_down_sync(0xffffffffu, v, 4);
    v += __shfl_down_sync(0xffffffffu, v, 2);
    v += __shfl_down_sync(0xffffffffu, v, 1);
    return v;
}

__device__ __forceinline__ float sigmoidf_fast(float x) {
    return __fdividef(1.0f, 1.0f + __expf(-x));
}

// ---------------------------------------------------------------- zero hist + accumulators
__global__ void k_zero() {
    size_t tid = blockIdx.x * blockDim.x + threadIdx.x;
    size_t stride = (size_t)gridDim.x * blockDim.x;
    float4* p = reinterpret_cast<float4*>(g_hist);
    for (size_t i = tid; i < sizeof(g_hist) / 16; i += stride)
        p[i] = make_float4(0.f, 0.f, 0.f, 0.f);
    if (blockIdx.x == 0 && threadIdx.x < 160) {
        int t = threadIdx.x;
        if (t < NSEG * 6) g_acc[t] = 0.f;
        if (t < Bx) g_seed_bg[t] = 0.f;
        if (t < NSEG) { g_fg_s[t] = 0.f; g_lov[t] = 0.f; }
    }
}

// ---------------------------------------------------------------- pass 1
__global__ void __launch_bounds__(256, 2) k_pass1(const float* __restrict__ pred,
                                                  const int* __restrict__ bbox,
                                                  const int* __restrict__ masks) {
    int b = blockIdx.x / BPB;
    int blk = blockIdx.x % BPB;
    const float* pb = pred + (size_t)b * 12 * HWx;
    const int* bbb = bbox + (size_t)b * 9 * HWx;
    const int* mb  = masks + (size_t)b * 8 * HWx;
    float* e0o = g_e0s + (size_t)b * HWx;
    float* e1o = g_e1s + (size_t)b * HWx;
    __half* sdo = g_seeds + (size_t)b * 8 * HWx;
    unsigned* mbo = g_mbits + (size_t)b * HWx / 4;

    float c_[8]  = {0,0,0,0,0,0,0,0};
    float ae0[8] = {0,0,0,0,0,0,0,0};
    float ae1[8] = {0,0,0,0,0,0,0,0};
    float as0[8] = {0,0,0,0,0,0,0,0};
    float as1[8] = {0,0,0,0,0,0,0,0};
    float qq[8]  = {0,0,0,0,0,0,0,0};
    float bg = 0.f;

    // grid-stride over float4-groups: exactly covers [0, HWx)
    for (int g = blk * 256 + threadIdx.x; g < HWx / 4; g += BPB * 256) {
        int hw = g * 4;
        int w = hw & (Wx - 1);
        int h = hw >> 10;
        float ybase = (float)h * (1.0f / 1023.0f);

        float4 p0 = *(const float4*)(pb + hw);
        float4 p1 = *(const float4*)(pb + HWx + hw);
        float e0[4], e1[4];
        e0[0] = tanhf(p0.x) + (float)(w + 0) * (2.0f / 2047.0f);
        e0[1] = tanhf(p0.y) + (float)(w + 1) * (2.0f / 2047.0f);
        e0[2] = tanhf(p0.z) + (float)(w + 2) * (2.0f / 2047.0f);
        e0[3] = tanhf(p0.w) + (float)(w + 3) * (2.0f / 2047.0f);
        e1[0] = tanhf(p1.x) + ybase;
        e1[1] = tanhf(p1.y) + ybase;
        e1[2] = tanhf(p1.z) + ybase;
        e1[3] = tanhf(p1.w) + ybase;
        *(float4*)(e0o + hw) = make_float4(e0[0], e0[1], e0[2], e0[3]);
        *(float4*)(e1o + hw) = make_float4(e1[0], e1[1], e1[2], e1[3]);

        float4 s0v = *(const float4*)(pb + 2 * HWx + hw);
        float4 s1v = *(const float4*)(pb + 3 * HWx + hw);
        float sg0[4] = {s0v.x, s0v.y, s0v.z, s0v.w};
        float sg1[4] = {s1v.x, s1v.y, s1v.z, s1v.w};
        float q4[4];
#pragma unroll
        for (int j = 0; j < 4; j++) q4[j] = fmaf(sg0[j], sg0[j], sg1[j] * sg1[j]);

#pragma unroll
        for (int c = 0; c < 8; c++) {
            float4 sv = *(const float4*)(pb + (4 + c) * HWx + hw);
            int4 bv = *(const int4*)(bbb + (1 + c) * HWx + hw);
            float s0 = sigmoidf_fast(sv.x);
            float s1 = sigmoidf_fast(sv.y);
            float s2 = sigmoidf_fast(sv.z);
            float s3 = sigmoidf_fast(sv.w);
            if (bv.x == 0) bg = fmaf(s0, s0, bg);
            if (bv.y == 0) bg = fmaf(s1, s1, bg);
            if (bv.z == 0) bg = fmaf(s2, s2, bg);
            if (bv.w == 0) bg = fmaf(s3, s3, bg);
            __half2 h01 = __floats2half2_rn(s0, s1);
            __half2 h23 = __floats2half2_rn(s2, s3);
            uint2 pk;
            pk.x = *reinterpret_cast<unsigned*>(&h01);
            pk.y = *reinterpret_cast<unsigned*>(&h23);
            *(uint2*)(sdo + (size_t)c * HWx + hw) = pk;
        }

        unsigned bits = 0;
#pragma unroll
        for (int n = 0; n < 8; n++) {
            int4 mv = *(const int4*)(mb + n * HWx + hw);
            float mf[4];
            mf[0] = (mv.x > 0) ? 1.f : 0.f;
            mf[1] = (mv.y > 0) ? 1.f : 0.f;
            mf[2] = (mv.z > 0) ? 1.f : 0.f;
            mf[3] = (mv.w > 0) ? 1.f : 0.f;
#pragma unroll
            for (int j = 0; j < 4; j++) {
                c_[n] += mf[j];
                ae0[n] = fmaf(mf[j], e0[j], ae0[n]);
                ae1[n] = fmaf(mf[j], e1[j], ae1[n]);
                as0[n] = fmaf(mf[j], sg0[j], as0[n]);
                as1[n] = fmaf(mf[j], sg1[j], as1[n]);
                qq[n]  = fmaf(mf[j], q4[j], qq[n]);
                if (mf[j] != 0.f) bits |= (1u << (n + j * 8));
            }
        }
        mbo[g] = bits;
    }

    bg = wred(bg);
    if ((threadIdx.x & 31) == 0) atomicAdd(&g_seed_bg[b], bg);
#pragma unroll
    for (int n = 0; n < 8; n++) {
        int seg = b * 8 + n;
        float v;
        v = wred(c_[n]);  if ((threadIdx.x & 31) == 0) atomicAdd(&g_acc[seg * 6 + 0], v);
        v = wred(ae0[n]); if ((threadIdx.x & 31) == 0) atomicAdd(&g_acc[seg * 6 + 1], v);
        v = wred(ae1[n]); if ((threadIdx.x & 31) == 0) atomicAdd(&g_acc[seg * 6 + 2], v);
        v = wred(as0[n]); if ((threadIdx.x & 31) == 0) atomicAdd(&g_acc[seg * 6 + 3], v);
        v = wred(as1[n]); if ((threadIdx.x & 31) == 0) atomicAdd(&g_acc[seg * 6 + 4], v);
        v = wred(qq[n]);  if ((threadIdx.x & 31) == 0) atomicAdd(&g_acc[seg * 6 + 5], v);
    }
}

// ---------------------------------------------------------------- per-instance params
__global__ void k_params() {
    int t = threadIdx.x;
    if (t < NSEG) {
        float cnt = g_acc[t * 6 + 0];
        float cs = fmaxf(cnt, 1.f);
        float inv = 1.f / cs;
        g_params[t * 4 + 0] = g_acc[t * 6 + 1] * inv;
        g_params[t * 4 + 1] = g_acc[t * 6 + 2] * inv;
        g_params[t * 4 + 2] = expf(g_acc[t * 6 + 3] * inv * 10.f);
        g_params[t * 4 + 3] = expf(g_acc[t * 6 + 4] * inv * 10.f);
    }
}

// ---------------------------------------------------------------- pass 2: dist, hist, seed_fg
__global__ void __launch_bounds__(256) k_pass3(const int* __restrict__ cls_ids) {
    int b = blockIdx.x / BPB;
    int blk = blockIdx.x % BPB;

    __shared__ float sp[8][4];
    __shared__ int sch[8];
    if (threadIdx.x < 32) {
        int n = threadIdx.x / 4, k = threadIdx.x % 4;
        sp[n][k] = g_params[(b * 8 + n) * 4 + k];
    }
    if (threadIdx.x < 8) sch[threadIdx.x] = cls_ids[b * 8 + threadIdx.x];
    __syncthreads();

    float c0[8], c1[8], sx0[8], sx1[8];
    const __half* sdp[8];
#pragma unroll
    for (int n = 0; n < 8; n++) {
        c0[n] = sp[n][0]; c1[n] = sp[n][1];
        sx0[n] = sp[n][2]; sx1[n] = sp[n][3];
        sdp[n] = g_seeds + ((size_t)b * 8 + sch[n]) * HWx;
    }
    float fa[8] = {0,0,0,0,0,0,0,0};

    const float* e0i = g_e0s + (size_t)b * HWx;
    const float* e1i = g_e1s + (size_t)b * HWx;
    const unsigned* mbi = g_mbits + (size_t)b * HWx / 4;
    unsigned long long* hb = &g_hist[(size_t)(b * 8) * NBINS];

    for (int g = blk * 256 + threadIdx.x; g < HWx / 4; g += BPB * 256) {
        int hw = g * 4;
        float4 E0 = *(const float4*)(e0i + hw);
        float4 E1 = *(const float4*)(e1i + hw);
        float e0[4] = {E0.x, E0.y, E0.z, E0.w};
        float e1[4] = {E1.x, E1.y, E1.z, E1.w};
        unsigned bits = mbi[g];

#pragma unroll
        for (int n = 0; n < 8; n++) {
            uint2 svp = *(const uint2*)(sdp[n] + hw);
            __half2 hA = *reinterpret_cast<__half2*>(&svp.x);
            __half2 hB = *reinterpret_cast<__half2*>(&svp.y);
            float2 fA = __half22float2(hA);
            float2 fB = __half22float2(hB);
            float sv[4] = {fA.x, fA.y, fB.x, fB.y};
#pragma unroll
            for (int j = 0; j < 4; j++) {
                int lab = (bits >> (n + j * 8)) & 1;
                float dx = e0[j] - c0[n];
                float dy = e1[j] - c1[n];
                float d2 = fmaf(dx * dx, sx0[n], dy * dy * sx1[n]);
                float dist = __expf(-d2);
                float e = lab ? fmaf(-2.f, dist, 2.f) : 2.f * dist;
                int bin = (int)(e * BIN_SCALE);
                bin = min(max(bin, 0), NBINS - 1);
                atomicAdd(&hb[(size_t)n * NBINS + bin],
                          lab ? (1ull << 32) : 1ull);
                float dd = sv[j] - dist;
                if (lab) fa[n] = fmaf(dd, dd, fa[n]);
            }
        }
    }
#pragma unroll
    for (int n = 0; n < 8; n++) {
        float v = wred(fa[n]);
        if ((threadIdx.x & 31) == 0) atomicAdd(&g_fg_s[b * 8 + n], v);
    }
}

// ---------------------------------------------------------------- Lovász via binned scan
__global__ void __launch_bounds__(1024) k_scan() {
    int seg = blockIdx.x;
    int tid = threadIdx.x;
    int warp = tid >> 5, lane = tid & 31;
    __shared__ unsigned long long wsum[32];
    __shared__ float rs[32];

    double Pd = (double)g_acc[seg * 6 + 0];
    unsigned carry_p = 0, carry_n = 0;
    double lov = 0.0;
    const unsigned long long* hp = &g_hist[(size_t)seg * NBINS];

    for (int it = 0; it < NBINS / 1024; it++) {
        int bin = NBINS - 1 - (it * 1024 + tid);
        unsigned long long pair = hp[bin];
        unsigned nn = (unsigned)(pair & 0xffffffffu);
        unsigned np = (unsigned)(pair >> 32);
        unsigned long long inc = pair;
#pragma unroll
        for (int o = 1; o < 32; o <<= 1) {
            unsigned long long t = __shfl_up_sync(0xffffffffu, inc, o);
            if (lane >= o) inc += t;
        }
        if (lane == 31) wsum[warp] = inc;
        __syncthreads();
        if (warp == 0) {
            unsigned long long wv = wsum[lane];
#pragma unroll
            for (int o = 1; o < 32; o <<= 1) {
                unsigned long long t = __shfl_up_sync(0xffffffffu, wv, o);
                if (lane >= o) wv += t;
            }
            wsum[lane] = wv;
        }
        __syncthreads();
        unsigned long long incl = inc + (warp > 0 ? wsum[warp - 1] : 0ull);
        unsigned long long total = wsum[31];
        unsigned cp1 = carry_p + (unsigned)(incl >> 32);
        unsigned cn1 = carry_n + (unsigned)(incl & 0xffffffffu);
        unsigned cp0 = cp1 - np;
        unsigned cn0 = cn1 - nn;
        if (np | nn) {
            double j1 = 1.0 - (Pd - (double)cp1) / fmax(Pd + (double)cn1, 1.0);
            double j0 = 1.0 - (Pd - (double)cp0) / fmax(Pd + (double)cn0, 1.0);
            lov += ((double)bin + 0.5) * (1.0 / 16384.0) * (j1 - j0);
        }
        carry_p += (unsigned)(total >> 32);
        carry_n += (unsigned)(total & 0xffffffffu);
        __syncthreads();
    }
    float lf = wred((float)lov);
    if (lane == 0) rs[warp] = lf;
    __syncthreads();
    if (tid < 32) {
        float v = wred(rs[tid]);
        if (tid == 0) g_lov[seg] = v;
    }
}

// ---------------------------------------------------------------- final combine
__global__ void k_final(const int* __restrict__ cls_ids, float* __restrict__ out) {
    if (threadIdx.x == 0 && blockIdx.x == 0) {
        float total = 0.f;
        for (int b = 0; b < Bx; b++) {
            float obj = 0.f, inst = 0.f, var = 0.f, fg = 0.f;
            for (int n = 0; n < 8; n++) {
                int seg = b * 8 + n;
                float cnt = g_acc[seg * 6 + 0];
                float valid = (cnt >= MINPIX) ? 1.f : 0.f;
                float cs = fmaxf(cnt, 1.f);
                float S0 = g_acc[seg * 6 + 3];
                float S1 = g_acc[seg * 6 + 4];
                float Q  = g_acc[seg * 6 + 5];
                float vi = (Q - (S0 * S0 + S1 * S1) / cs) / (2.f * cs);
                obj += valid;
                inst += g_lov[seg] * valid;
                var += vi * valid;
                fg += FGW[cls_ids[seg]] * g_fg_s[seg] * valid;
            }
            float os = fmaxf(obj, 1.f);
            float seed_l = (g_seed_bg[b] + fg) * (1.0f / (float)HWx);
            total += inst / os + 10.f * (var / os) + seed_l;
        }
        out[0] = total * 0.5f;
    }
}

// ---------------------------------------------------------------- launch
extern "C" void kernel_launch(void* const* d_in, const int* in_sizes, int n_in,
                              void* d_out, int out_size) {
    const float* pred = (const float*)d_in[0];
    const int* bbox   = (const int*)d_in[1];
    const int* masks  = (const int*)d_in[2];
    const int* cls    = (const int*)d_in[3];
    (void)in_sizes; (void)n_in; (void)out_size;

    k_zero<<<512, 256>>>();
    k_pass1<<<Bx * BPB, 256>>>(pred, bbox, masks);
    k_params<<<1, 32>>>();
    k_pass3<<<Bx * BPB, 256>>>(cls);
    k_scan<<<NSEG, 1024>>>();
    k_final<<<1, 32>>>(cls, (float*)d_out);
}